// round 1
// baseline (speedup 1.0000x reference)
#include <cuda_runtime.h>
#include <math.h>

// Problem constants (fixed shapes from reference setup_inputs)
#define BATCH 2
#define IH 1080
#define IW 1920
#define SH 540
#define SW 960

#define N_SMALL (BATCH * SH * SW)
#define N_FULL  (BATCH * IH * IW)

// Scratch (allocation-free: __device__ globals)
__device__ float g_luma[N_SMALL];          // luma @540x960, later reused as blurred edge
__device__ float g_sxy[2 * N_SMALL];       // 2-channel sobel-x intermediate
__device__ float g_edge[N_SMALL];          // edge magnitude
__device__ float g_tmp[N_SMALL];           // blur temp
__device__ float g_grad_s[2 * N_SMALL];    // small gradient field (xg, yg)
__device__ float g_grad_f[2 * N_FULL];     // upsampled gradient field

__device__ __forceinline__ float clampf(float v, float lo, float hi) {
    return fminf(fmaxf(v, lo), hi);
}

// 1-D bilinear along x (row y is integer), clamped (border padding, align_corners)
__device__ __forceinline__ float sampX(const float* __restrict__ p, int y, float x, int Wd) {
    x = clampf(x, 0.0f, (float)(Wd - 1));
    int x0 = (int)floorf(x);
    int x1 = min(x0 + 1, Wd - 1);
    float w = x - (float)x0;
    const float* row = p + y * Wd;
    return row[x0] * (1.0f - w) + row[x1] * w;
}

// 1-D bilinear along y (column x is integer), clamped
__device__ __forceinline__ float sampY(const float* __restrict__ p, float y, int x, int Hd, int Wd) {
    y = clampf(y, 0.0f, (float)(Hd - 1));
    int y0 = (int)floorf(y);
    int y1 = min(y0 + 1, Hd - 1);
    float w = y - (float)y0;
    return p[y0 * Wd + x] * (1.0f - w) + p[y1 * Wd + x] * w;
}

// ---------------------------------------------------------------------------
// Stage 1: luma + bilinear downscale 1080x1920 -> 540x960 (align_corners)
// ---------------------------------------------------------------------------
__global__ void k_luma_down(const float* __restrict__ img) {
    int i = blockIdx.x * blockDim.x + threadIdx.x;
    if (i >= N_SMALL) return;
    int x = i % SW;
    int y = (i / SW) % SH;
    int b = i / (SW * SH);

    float gy = -1.0f + 2.0f * (float)y / (float)(SH - 1);
    float gx = -1.0f + 2.0f * (float)x / (float)(SW - 1);
    float fy = clampf((gy + 1.0f) * 0.5f * (float)(IH - 1), 0.0f, (float)(IH - 1));
    float fx = clampf((gx + 1.0f) * 0.5f * (float)(IW - 1), 0.0f, (float)(IW - 1));
    int y0 = (int)floorf(fy), x0 = (int)floorf(fx);
    int y1 = min(y0 + 1, IH - 1), x1 = min(x0 + 1, IW - 1);
    float wy = fy - (float)y0, wx = fx - (float)x0;

    const float* r  = img + ((size_t)b * 3 + 0) * IH * IW;
    const float* g  = img + ((size_t)b * 3 + 1) * IH * IW;
    const float* bl = img + ((size_t)b * 3 + 2) * IH * IW;

    int o00 = y0 * IW + x0, o01 = y0 * IW + x1, o10 = y1 * IW + x0, o11 = y1 * IW + x1;
    float v00 = 0.299f * r[o00] + 0.587f * g[o00] + 0.114f * bl[o00];
    float v01 = 0.299f * r[o01] + 0.587f * g[o01] + 0.114f * bl[o01];
    float v10 = 0.299f * r[o10] + 0.587f * g[o10] + 0.114f * bl[o10];
    float v11 = 0.299f * r[o11] + 0.587f * g[o11] + 0.114f * bl[o11];

    g_luma[i] = (v00 * (1.0f - wx) + v01 * wx) * (1.0f - wy)
              + (v10 * (1.0f - wx) + v11 * wx) * wy;
}

// ---------------------------------------------------------------------------
// sobel_x: in [B,1,SH,SW] -> out [B,2,SH,SW]; fractional x shift = offset*(SW-1)/SW px
// ---------------------------------------------------------------------------
__global__ void k_sobelx(const float* __restrict__ in, float* __restrict__ out, float offset) {
    int i = blockIdx.x * blockDim.x + threadIdx.x;
    if (i >= N_SMALL) return;
    int x = i % SW;
    int y = (i / SW) % SH;
    int b = i / (SW * SH);

    const float* p = in + b * SH * SW;
    float ddx = 2.0f * offset / (float)SW;          // normalized shift
    float s = ddx * 0.5f * (float)(SW - 1);         // pixels
    float xf = (float)x;
    float left  = sampX(p, y, xf - s, SW);
    float right = sampX(p, y, xf + s, SW);
    float c = p[y * SW + x];

    out[(b * 2 + 0) * SH * SW + y * SW + x] = -left + right;
    out[(b * 2 + 1) * SH * SW + y * SW + x] = left + 2.0f * c + right;
}

// ---------------------------------------------------------------------------
// sobel_y magnitude: in [B,2,SH,SW] -> out [B,1,SH,SW], (sqrt(xg^2+yg^2))^0.7
// ---------------------------------------------------------------------------
__global__ void k_sobely_mag(const float* __restrict__ sxy, float* __restrict__ out, float offset) {
    int i = blockIdx.x * blockDim.x + threadIdx.x;
    if (i >= N_SMALL) return;
    int x = i % SW;
    int y = (i / SW) % SH;
    int b = i / (SW * SH);

    const float* c0 = sxy + (b * 2 + 0) * SH * SW;
    const float* c1 = sxy + (b * 2 + 1) * SH * SW;
    float ddy = 2.0f * offset / (float)SH;
    float s = ddy * 0.5f * (float)(SH - 1);
    float yf = (float)y;

    float top0 = sampY(c0, yf - s, x, SH, SW);
    float bot0 = sampY(c0, yf + s, x, SH, SW);
    float cc0 = c0[y * SW + x];
    float xg = (top0 + 2.0f * cc0 + bot0) * 0.125f;

    float top1 = sampY(c1, yf - s, x, SH, SW);
    float bot1 = sampY(c1, yf + s, x, SH, SW);
    float yg = (-top1 + bot1) * 0.125f;

    out[b * SH * SW + y * SW + x] = powf(sqrtf(xg * xg + yg * yg), 0.7f);
}

// ---------------------------------------------------------------------------
// sobel_y vector form: in [B,2,SH,SW] -> out [B,2,SH,SW] = [xg, yg]
// ---------------------------------------------------------------------------
__global__ void k_sobely_vec(const float* __restrict__ sxy, float* __restrict__ out, float offset) {
    int i = blockIdx.x * blockDim.x + threadIdx.x;
    if (i >= N_SMALL) return;
    int x = i % SW;
    int y = (i / SW) % SH;
    int b = i / (SW * SH);

    const float* c0 = sxy + (b * 2 + 0) * SH * SW;
    const float* c1 = sxy + (b * 2 + 1) * SH * SW;
    float ddy = 2.0f * offset / (float)SH;
    float s = ddy * 0.5f * (float)(SH - 1);
    float yf = (float)y;

    float top0 = sampY(c0, yf - s, x, SH, SW);
    float bot0 = sampY(c0, yf + s, x, SH, SW);
    float cc0 = c0[y * SW + x];
    float xg = (top0 + 2.0f * cc0 + bot0) * 0.125f;

    float top1 = sampY(c1, yf - s, x, SH, SW);
    float bot1 = sampY(c1, yf + s, x, SH, SW);
    float yg = (-top1 + bot1) * 0.125f;

    out[(b * 2 + 0) * SH * SW + y * SW + x] = xg;
    out[(b * 2 + 1) * SH * SW + y * SW + x] = yg;
}

// ---------------------------------------------------------------------------
// Gaussian blur sigma=1.0, ks=5, edge (replicate) padding, separable
// weights: exp(-0.5 t^2)/sum, t=-2..2
// ---------------------------------------------------------------------------
#define GW0 0.05448868f
#define GW1 0.24420135f
#define GW2 0.40261995f

__global__ void k_blur_h(const float* __restrict__ in, float* __restrict__ out) {
    int i = blockIdx.x * blockDim.x + threadIdx.x;
    if (i >= N_SMALL) return;
    int x = i % SW;
    int y = (i / SW) % SH;
    int b = i / (SW * SH);
    const float* row = in + (b * SH + y) * SW;
    float v = GW0 * row[max(x - 2, 0)]
            + GW1 * row[max(x - 1, 0)]
            + GW2 * row[x]
            + GW1 * row[min(x + 1, SW - 1)]
            + GW0 * row[min(x + 2, SW - 1)];
    out[i] = v;
}

__global__ void k_blur_v(const float* __restrict__ in, float* __restrict__ out) {
    int i = blockIdx.x * blockDim.x + threadIdx.x;
    if (i >= N_SMALL) return;
    int x = i % SW;
    int y = (i / SW) % SH;
    int b = i / (SW * SH);
    const float* pl = in + b * SH * SW;
    float v = GW0 * pl[max(y - 2, 0) * SW + x]
            + GW1 * pl[max(y - 1, 0) * SW + x]
            + GW2 * pl[y * SW + x]
            + GW1 * pl[min(y + 1, SH - 1) * SW + x]
            + GW0 * pl[min(y + 2, SH - 1) * SW + x];
    out[i] = v;
}

// ---------------------------------------------------------------------------
// Bilinear upsample grad field [B,2,SH,SW] -> [B,2,IH,IW] (align_corners)
// ---------------------------------------------------------------------------
__global__ void k_upsample(const float* __restrict__ gs, float* __restrict__ gf) {
    int i = blockIdx.x * blockDim.x + threadIdx.x;
    if (i >= N_FULL) return;
    int x = i % IW;
    int y = (i / IW) % IH;
    int b = i / (IW * IH);

    float gyn = -1.0f + 2.0f * (float)y / (float)(IH - 1);
    float gxn = -1.0f + 2.0f * (float)x / (float)(IW - 1);
    float fy = clampf((gyn + 1.0f) * 0.5f * (float)(SH - 1), 0.0f, (float)(SH - 1));
    float fx = clampf((gxn + 1.0f) * 0.5f * (float)(SW - 1), 0.0f, (float)(SW - 1));
    int y0 = (int)floorf(fy), x0 = (int)floorf(fx);
    int y1 = min(y0 + 1, SH - 1), x1 = min(x0 + 1, SW - 1);
    float wy = fy - (float)y0, wx = fx - (float)x0;

    #pragma unroll
    for (int c = 0; c < 2; c++) {
        const float* p = gs + (b * 2 + c) * SH * SW;
        float v00 = p[y0 * SW + x0], v01 = p[y0 * SW + x1];
        float v10 = p[y1 * SW + x0], v11 = p[y1 * SW + x1];
        gf[(b * 2 + c) * IH * IW + y * IW + x] =
            (v00 * (1.0f - wx) + v01 * wx) * (1.0f - wy)
          + (v10 * (1.0f - wx) + v11 * wx) * wy;
    }
}

// ---------------------------------------------------------------------------
// Warp: 6 fixed-point iterations over the full-res grad field, then sample image
// ---------------------------------------------------------------------------
__global__ void k_warp(const float* __restrict__ img, const float* __restrict__ gf,
                       float* __restrict__ out) {
    int i = blockIdx.x * blockDim.x + threadIdx.x;
    if (i >= N_FULL) return;
    int X = i % IW;
    int Y = (i / IW) % IH;
    int b = i / (IW * IH);

    float px = -1.0f + 2.0f * (float)X / (float)(IW - 1);
    float py = -1.0f + 2.0f * (float)Y / (float)(IH - 1);

    const float relstr = ((float)IH / 1080.0f) * 0.1f;
    const float stepx = 2.0f / (float)IW * relstr;
    const float stepy = 2.0f / (float)IH * relstr;

    const float* gcx = gf + (b * 2 + 0) * IH * IW;
    const float* gcy = gf + (b * 2 + 1) * IH * IW;

    #pragma unroll
    for (int it = 0; it < 6; ++it) {
        float fx = clampf((px + 1.0f) * 0.5f * (float)(IW - 1), 0.0f, (float)(IW - 1));
        float fy = clampf((py + 1.0f) * 0.5f * (float)(IH - 1), 0.0f, (float)(IH - 1));
        int x0 = (int)floorf(fx), y0 = (int)floorf(fy);
        int x1 = min(x0 + 1, IW - 1), y1 = min(y0 + 1, IH - 1);
        float wx = fx - (float)x0, wy = fy - (float)y0;
        int o00 = y0 * IW + x0, o01 = y0 * IW + x1, o10 = y1 * IW + x0, o11 = y1 * IW + x1;

        float dx = (gcx[o00] * (1.0f - wx) + gcx[o01] * wx) * (1.0f - wy)
                 + (gcx[o10] * (1.0f - wx) + gcx[o11] * wx) * wy;
        float dy = (gcy[o00] * (1.0f - wx) + gcy[o01] * wx) * (1.0f - wy)
                 + (gcy[o10] * (1.0f - wx) + gcy[o11] * wx) * wy;

        float len = sqrtf(dx * dx + dy * dy) + 0.01f;
        px -= dx / len * stepx;
        py -= dy / len * stepy;
    }

    float fx = clampf((px + 1.0f) * 0.5f * (float)(IW - 1), 0.0f, (float)(IW - 1));
    float fy = clampf((py + 1.0f) * 0.5f * (float)(IH - 1), 0.0f, (float)(IH - 1));
    int x0 = (int)floorf(fx), y0 = (int)floorf(fy);
    int x1 = min(x0 + 1, IW - 1), y1 = min(y0 + 1, IH - 1);
    float wx = fx - (float)x0, wy = fy - (float)y0;
    int o00 = y0 * IW + x0, o01 = y0 * IW + x1, o10 = y1 * IW + x0, o11 = y1 * IW + x1;

    #pragma unroll
    for (int c = 0; c < 3; ++c) {
        const float* p = img + ((size_t)b * 3 + c) * IH * IW;
        float v = (p[o00] * (1.0f - wx) + p[o01] * wx) * (1.0f - wy)
                + (p[o10] * (1.0f - wx) + p[o11] * wx) * wy;
        out[((size_t)b * 3 + c) * IH * IW + (size_t)Y * IW + X] = clampf(v, 0.0f, 1.0f);
    }
}

// ---------------------------------------------------------------------------
extern "C" void kernel_launch(void* const* d_in, const int* in_sizes, int n_in,
                              void* d_out, int out_size) {
    const float* img = (const float*)d_in[0];
    float* out = (float*)d_out;

    float *p_luma, *p_sxy, *p_edge, *p_tmp, *p_grad_s, *p_grad_f;
    cudaGetSymbolAddress((void**)&p_luma, g_luma);
    cudaGetSymbolAddress((void**)&p_sxy, g_sxy);
    cudaGetSymbolAddress((void**)&p_edge, g_edge);
    cudaGetSymbolAddress((void**)&p_tmp, g_tmp);
    cudaGetSymbolAddress((void**)&p_grad_s, g_grad_s);
    cudaGetSymbolAddress((void**)&p_grad_f, g_grad_f);

    const int T = 256;
    int gs = (N_SMALL + T - 1) / T;
    int gfz = (N_FULL + T - 1) / T;

    k_luma_down<<<gs, T>>>(img);
    k_sobelx<<<gs, T>>>(p_luma, p_sxy, 1.0f);
    k_sobely_mag<<<gs, T>>>(p_sxy, p_edge, 1.0f);
    k_blur_h<<<gs, T>>>(p_edge, p_tmp);
    k_blur_v<<<gs, T>>>(p_tmp, p_luma);          // p_luma reused as blurred edge
    k_sobelx<<<gs, T>>>(p_luma, p_sxy, 0.5f);
    k_sobely_vec<<<gs, T>>>(p_sxy, p_grad_s, 0.5f);
    k_upsample<<<gfz, T>>>(p_grad_s, p_grad_f);
    k_warp<<<gfz, T>>>(img, p_grad_f, out);
}

// round 2
// speedup vs baseline: 1.3382x; 1.3382x over previous
#include <cuda_runtime.h>
#include <math.h>

#define BATCH 2
#define IH 1080
#define IW 1920
#define SH 540
#define SW 960

#define N_SMALL (BATCH * SH * SW)
#define N_FULL  (BATCH * IH * IW)

// Scratch (allocation-free: __device__ globals)
__device__ float  g_luma[N_SMALL];         // luma @540x960
__device__ float  g_edge[N_SMALL];         // edge magnitude
__device__ float  g_tmp[N_SMALL];          // blurred edge
__device__ float2 g_grad_s[N_SMALL];       // small gradient field, interleaved (xg, yg)
__device__ float2 g_grad_f[N_FULL];        // upsampled gradient field, interleaved

__device__ __forceinline__ float clampf(float v, float lo, float hi) {
    return fminf(fmaxf(v, lo), hi);
}

// Gaussian sigma=1.0, ks=5 weights
#define GW0 0.05448868f
#define GW1 0.24420135f
#define GW2 0.40261995f

// ---------------------------------------------------------------------------
// Stage 1: luma + bilinear downscale 1080x1920 -> 540x960 (align_corners)
// ---------------------------------------------------------------------------
__global__ void k_luma_down(const float* __restrict__ img) {
    int i = blockIdx.x * blockDim.x + threadIdx.x;
    if (i >= N_SMALL) return;
    int x = i % SW;
    int y = (i / SW) % SH;
    int b = i / (SW * SH);

    float gy = -1.0f + 2.0f * (float)y / (float)(SH - 1);
    float gx = -1.0f + 2.0f * (float)x / (float)(SW - 1);
    float fy = clampf((gy + 1.0f) * 0.5f * (float)(IH - 1), 0.0f, (float)(IH - 1));
    float fx = clampf((gx + 1.0f) * 0.5f * (float)(IW - 1), 0.0f, (float)(IW - 1));
    int y0 = (int)floorf(fy), x0 = (int)floorf(fx);
    int y1 = min(y0 + 1, IH - 1), x1 = min(x0 + 1, IW - 1);
    float wy = fy - (float)y0, wx = fx - (float)x0;

    const float* r  = img + ((size_t)b * 3 + 0) * IH * IW;
    const float* g  = img + ((size_t)b * 3 + 1) * IH * IW;
    const float* bl = img + ((size_t)b * 3 + 2) * IH * IW;

    int o00 = y0 * IW + x0, o01 = y0 * IW + x1, o10 = y1 * IW + x0, o11 = y1 * IW + x1;
    float v00 = 0.299f * r[o00] + 0.587f * g[o00] + 0.114f * bl[o00];
    float v01 = 0.299f * r[o01] + 0.587f * g[o01] + 0.114f * bl[o01];
    float v10 = 0.299f * r[o10] + 0.587f * g[o10] + 0.114f * bl[o10];
    float v11 = 0.299f * r[o11] + 0.587f * g[o11] + 0.114f * bl[o11];

    g_luma[i] = (v00 * (1.0f - wx) + v01 * wx) * (1.0f - wy)
              + (v10 * (1.0f - wx) + v11 * wx) * wy;
}

// ---------------------------------------------------------------------------
// Fused sobel_x + sobel_y (exact linear-operator composition).
// Produces (xg, yg) for a given fractional offset.
//   ch0(R) = -L(x-sx,R) + L(x+sx,R)          (x-derivative)
//   ch1(R) =  L(x-sx,R) + 2 L(x,R) + L(x+sx,R)
//   xg = (ch0(y-sy) + 2 ch0(y) + ch0(y+sy)) / 8   (vertical lerp for frac rows)
//   yg = (-ch1(y-sy) + ch1(y+sy)) / 8
// ---------------------------------------------------------------------------
__device__ __forceinline__ void sobel_pair(const float* __restrict__ p, int x, int y,
                                           float sx, float sy, float& xg, float& yg) {
    float xl = clampf((float)x - sx, 0.0f, (float)(SW - 1));
    float xr = clampf((float)x + sx, 0.0f, (float)(SW - 1));
    int xl0 = (int)floorf(xl); int xl1 = min(xl0 + 1, SW - 1); float wl = xl - (float)xl0;
    int xr0 = (int)floorf(xr); int xr1 = min(xr0 + 1, SW - 1); float wr = xr - (float)xr0;

    float yt = clampf((float)y - sy, 0.0f, (float)(SH - 1));
    float yb = clampf((float)y + sy, 0.0f, (float)(SH - 1));
    int yt0 = (int)floorf(yt); int yt1 = min(yt0 + 1, SH - 1); float wt = yt - (float)yt0;
    int yb0 = (int)floorf(yb); int yb1 = min(yb0 + 1, SH - 1); float wb = yb - (float)yb0;

    // horizontal samples l, c, r at an integer row
    auto hrow = [&](int R, float& l, float& c, float& r) {
        const float* row = p + R * SW;
        l = row[xl0] * (1.0f - wl) + row[xl1] * wl;
        c = row[x];
        r = row[xr0] * (1.0f - wr) + row[xr1] * wr;
    };

    float lt0, ct0, rt0, lt1, ct1, rt1, lc, cc, rc, lb0, cb0, rb0, lb1, cb1, rb1;
    hrow(yt0, lt0, ct0, rt0);
    hrow(yt1, lt1, ct1, rt1);
    hrow(y,   lc,  cc,  rc);
    hrow(yb0, lb0, cb0, rb0);
    hrow(yb1, lb1, cb1, rb1);

    // ch0 at frac top/bot and center
    float ch0_t = (-lt0 + rt0) * (1.0f - wt) + (-lt1 + rt1) * wt;
    float ch0_b = (-lb0 + rb0) * (1.0f - wb) + (-lb1 + rb1) * wb;
    float ch0_c = -lc + rc;
    // ch1 at frac top/bot
    float ch1_t = (lt0 + 2.0f * ct0 + rt0) * (1.0f - wt) + (lt1 + 2.0f * ct1 + rt1) * wt;
    float ch1_b = (lb0 + 2.0f * cb0 + rb0) * (1.0f - wb) + (lb1 + 2.0f * cb1 + rb1) * wb;

    xg = (ch0_t + 2.0f * ch0_c + ch0_b) * 0.125f;
    yg = (-ch1_t + ch1_b) * 0.125f;
}

__global__ void k_sobel_edge(const float* __restrict__ in, float* __restrict__ out,
                             float sx, float sy) {
    int i = blockIdx.x * blockDim.x + threadIdx.x;
    if (i >= N_SMALL) return;
    int x = i % SW;
    int y = (i / SW) % SH;
    int b = i / (SW * SH);
    float xg, yg;
    sobel_pair(in + b * SH * SW, x, y, sx, sy, xg, yg);
    out[i] = powf(sqrtf(xg * xg + yg * yg), 0.7f);
}

__global__ void k_sobel_grad(const float* __restrict__ in, float2* __restrict__ out,
                             float sx, float sy) {
    int i = blockIdx.x * blockDim.x + threadIdx.x;
    if (i >= N_SMALL) return;
    int x = i % SW;
    int y = (i / SW) % SH;
    int b = i / (SW * SH);
    float xg, yg;
    sobel_pair(in + b * SH * SW, x, y, sx, sy, xg, yg);
    out[i] = make_float2(xg, yg);
}

// ---------------------------------------------------------------------------
// Fused separable Gaussian blur (5x5 outer-product == h then v with edge pad)
// Tile 32x10, smem halo 2 on each side.
// ---------------------------------------------------------------------------
#define BBX 32
#define BBY 10
__global__ void k_blur(const float* __restrict__ in, float* __restrict__ out) {
    __shared__ float s[BBY + 4][BBX + 4];
    int b = blockIdx.z;
    int tx0 = blockIdx.x * BBX;
    int ty0 = blockIdx.y * BBY;
    const float* pl = in + b * SH * SW;

    int tid = threadIdx.y * BBX + threadIdx.x;
    const int NLOAD = (BBY + 4) * (BBX + 4);
    for (int idx = tid; idx < NLOAD; idx += BBX * BBY) {
        int lx = idx % (BBX + 4);
        int ly = idx / (BBX + 4);
        int gx = min(max(tx0 - 2 + lx, 0), SW - 1);
        int gy = min(max(ty0 - 2 + ly, 0), SH - 1);
        s[ly][lx] = pl[gy * SW + gx];
    }
    __syncthreads();

    int lx = threadIdx.x, ly = threadIdx.y;
    const float w[5] = {GW0, GW1, GW2, GW1, GW0};
    float acc = 0.0f;
    #pragma unroll
    for (int j = 0; j < 5; ++j) {
        float h = 0.0f;
        #pragma unroll
        for (int ii = 0; ii < 5; ++ii)
            h = fmaf(w[ii], s[ly + j][lx + ii], h);
        acc = fmaf(w[j], h, acc);
    }
    out[(b * SH + ty0 + ly) * SW + tx0 + lx] = acc;
}

// ---------------------------------------------------------------------------
// Bilinear upsample grad field (interleaved) 540x960 -> 1080x1920, 2 px/thread
// ---------------------------------------------------------------------------
__global__ void k_upsample(const float2* __restrict__ gs, float2* __restrict__ gf) {
    int i = blockIdx.x * blockDim.x + threadIdx.x;
    const int HALFW = IW / 2;
    if (i >= BATCH * IH * HALFW) return;
    int xp = (i % HALFW) * 2;
    int y  = (i / HALFW) % IH;
    int b  = i / (HALFW * IH);

    float gyn = -1.0f + 2.0f * (float)y / (float)(IH - 1);
    float fy = clampf((gyn + 1.0f) * 0.5f * (float)(SH - 1), 0.0f, (float)(SH - 1));
    int y0 = (int)floorf(fy);
    int y1 = min(y0 + 1, SH - 1);
    float wy = fy - (float)y0;

    const float2* p0 = gs + b * SH * SW + y0 * SW;
    const float2* p1 = gs + b * SH * SW + y1 * SW;

    float2 res[2];
    #pragma unroll
    for (int k = 0; k < 2; ++k) {
        int x = xp + k;
        float gxn = -1.0f + 2.0f * (float)x / (float)(IW - 1);
        float fx = clampf((gxn + 1.0f) * 0.5f * (float)(SW - 1), 0.0f, (float)(SW - 1));
        int x0 = (int)floorf(fx);
        int x1 = min(x0 + 1, SW - 1);
        float wx = fx - (float)x0;
        float2 a00 = p0[x0], a01 = p0[x1], a10 = p1[x0], a11 = p1[x1];
        float vx = (a00.x * (1.0f - wx) + a01.x * wx) * (1.0f - wy)
                 + (a10.x * (1.0f - wx) + a11.x * wx) * wy;
        float vy = (a00.y * (1.0f - wx) + a01.y * wx) * (1.0f - wy)
                 + (a10.y * (1.0f - wx) + a11.y * wx) * wy;
        res[k] = make_float2(vx, vy);
    }
    // coalesced 16B store (xp even)
    float4* dst = (float4*)(gf + (size_t)(b * IH + y) * IW + xp);
    *dst = make_float4(res[0].x, res[0].y, res[1].x, res[1].y);
}

// ---------------------------------------------------------------------------
// Warp: 6 fixed-point iterations + final image sample. 2 px/thread.
// ---------------------------------------------------------------------------
__global__ void k_warp(const float* __restrict__ img, const float2* __restrict__ gf,
                       float* __restrict__ out) {
    int i = blockIdx.x * blockDim.x + threadIdx.x;
    const int HALFW = IW / 2;
    if (i >= BATCH * IH * HALFW) return;
    int Xp = (i % HALFW) * 2;
    int Y  = (i / HALFW) % IH;
    int b  = i / (HALFW * IH);

    const float relstr = ((float)IH / 1080.0f) * 0.1f;
    const float stepx = 2.0f / (float)IW * relstr;
    const float stepy = 2.0f / (float)IH * relstr;

    const float2* g = gf + (size_t)b * IH * IW;

    float px[2], py[2];
    #pragma unroll
    for (int k = 0; k < 2; ++k) {
        px[k] = -1.0f + 2.0f * (float)(Xp + k) / (float)(IW - 1);
        py[k] = -1.0f + 2.0f * (float)Y / (float)(IH - 1);
    }

    #pragma unroll
    for (int it = 0; it < 6; ++it) {
        #pragma unroll
        for (int k = 0; k < 2; ++k) {
            float fx = clampf((px[k] + 1.0f) * 0.5f * (float)(IW - 1), 0.0f, (float)(IW - 1));
            float fy = clampf((py[k] + 1.0f) * 0.5f * (float)(IH - 1), 0.0f, (float)(IH - 1));
            int x0 = (int)floorf(fx), y0 = (int)floorf(fy);
            int x1 = min(x0 + 1, IW - 1), y1 = min(y0 + 1, IH - 1);
            float wx = fx - (float)x0, wy = fy - (float)y0;

            float2 a00 = g[y0 * IW + x0], a01 = g[y0 * IW + x1];
            float2 a10 = g[y1 * IW + x0], a11 = g[y1 * IW + x1];
            float dx = (a00.x * (1.0f - wx) + a01.x * wx) * (1.0f - wy)
                     + (a10.x * (1.0f - wx) + a11.x * wx) * wy;
            float dy = (a00.y * (1.0f - wx) + a01.y * wx) * (1.0f - wy)
                     + (a10.y * (1.0f - wx) + a11.y * wx) * wy;

            float len = sqrtf(dx * dx + dy * dy) + 0.01f;
            float inv = __fdividef(1.0f, len);
            px[k] -= dx * inv * stepx;
            py[k] -= dy * inv * stepy;
        }
    }

    // final sample per pixel
    int o00[2], o01[2], o10[2], o11[2];
    float wx[2], wy[2];
    #pragma unroll
    for (int k = 0; k < 2; ++k) {
        float fx = clampf((px[k] + 1.0f) * 0.5f * (float)(IW - 1), 0.0f, (float)(IW - 1));
        float fy = clampf((py[k] + 1.0f) * 0.5f * (float)(IH - 1), 0.0f, (float)(IH - 1));
        int x0 = (int)floorf(fx), y0 = (int)floorf(fy);
        int x1 = min(x0 + 1, IW - 1), y1 = min(y0 + 1, IH - 1);
        wx[k] = fx - (float)x0; wy[k] = fy - (float)y0;
        o00[k] = y0 * IW + x0; o01[k] = y0 * IW + x1;
        o10[k] = y1 * IW + x0; o11[k] = y1 * IW + x1;
    }

    #pragma unroll
    for (int c = 0; c < 3; ++c) {
        const float* p = img + ((size_t)b * 3 + c) * IH * IW;
        float v[2];
        #pragma unroll
        for (int k = 0; k < 2; ++k) {
            float vv = (p[o00[k]] * (1.0f - wx[k]) + p[o01[k]] * wx[k]) * (1.0f - wy[k])
                     + (p[o10[k]] * (1.0f - wx[k]) + p[o11[k]] * wx[k]) * wy[k];
            v[k] = clampf(vv, 0.0f, 1.0f);
        }
        float2* dst = (float2*)(out + ((size_t)b * 3 + c) * IH * IW + (size_t)Y * IW + Xp);
        *dst = make_float2(v[0], v[1]);
    }
}

// ---------------------------------------------------------------------------
extern "C" void kernel_launch(void* const* d_in, const int* in_sizes, int n_in,
                              void* d_out, int out_size) {
    const float* img = (const float*)d_in[0];
    float* out = (float*)d_out;

    float *p_luma, *p_edge, *p_tmp;
    float2 *p_grad_s, *p_grad_f;
    cudaGetSymbolAddress((void**)&p_luma, g_luma);
    cudaGetSymbolAddress((void**)&p_edge, g_edge);
    cudaGetSymbolAddress((void**)&p_tmp, g_tmp);
    cudaGetSymbolAddress((void**)&p_grad_s, g_grad_s);
    cudaGetSymbolAddress((void**)&p_grad_f, g_grad_f);

    const int T = 256;
    int gs = (N_SMALL + T - 1) / T;
    int gh = (BATCH * IH * (IW / 2) + T - 1) / T;

    // sobel pixel shifts: offset*(W-1)/W, offset*(H-1)/H
    const float sx1 = 1.0f * (float)(SW - 1) / (float)SW;
    const float sy1 = 1.0f * (float)(SH - 1) / (float)SH;
    const float sx2 = 0.5f * (float)(SW - 1) / (float)SW;
    const float sy2 = 0.5f * (float)(SH - 1) / (float)SH;

    k_luma_down<<<gs, T>>>(img);
    k_sobel_edge<<<gs, T>>>(p_luma, p_edge, sx1, sy1);
    dim3 bb(BBX, BBY);
    dim3 gb(SW / BBX, SH / BBY, BATCH);
    k_blur<<<gb, bb>>>(p_edge, p_tmp);
    k_sobel_grad<<<gs, T>>>(p_tmp, p_grad_s, sx2, sy2);
    k_upsample<<<gh, T>>>(p_grad_s, p_grad_f);
    k_warp<<<gh, T>>>(img, p_grad_f, out);
}